// round 17
// baseline (speedup 1.0000x reference)
#include <cuda_runtime.h>
#include <cuda_bf16.h>
#include <cstdint>

#define BSZ 4
#define CCH 256
#define HH 64
#define WW 64
#define HWN 4096
#define GG 4
#define CG 64

#define MP_STRIDE (BSZ*64*HWN)
#define OP_STRIDE (BSZ*72*HWN)

// ---------------- helpers ----------------
__device__ __forceinline__ uint32_t smem_u32(const void* p){
  uint32_t a; asm("{ .reg .u64 t; cvta.to.shared.u64 t, %1; cvt.u32.u64 %0, t; }" : "=r"(a) : "l"(p)); return a;
}
__device__ __forceinline__ void ldsm_x4(uint32_t* r, uint32_t a) {
    asm volatile("ldmatrix.sync.aligned.m8n8.x4.shared.b16 {%0,%1,%2,%3}, [%4];"
        : "=r"(r[0]), "=r"(r[1]), "=r"(r[2]), "=r"(r[3]) : "r"(a));
}
__device__ __forceinline__ void ldsm_x2(uint32_t* r, uint32_t a) {
    asm volatile("ldmatrix.sync.aligned.m8n8.x2.shared.b16 {%0,%1}, [%2];"
        : "=r"(r[0]), "=r"(r[1]) : "r"(a));
}
__device__ __forceinline__ void mma_bf16(float* d, const uint32_t* a, uint32_t b0, uint32_t b1) {
    asm volatile("mma.sync.aligned.m16n8k16.row.col.f32.bf16.bf16.f32 "
        "{%0,%1,%2,%3}, {%4,%5,%6,%7}, {%8,%9}, {%0,%1,%2,%3};"
        : "+f"(d[0]), "+f"(d[1]), "+f"(d[2]), "+f"(d[3])
        : "r"(a[0]), "r"(a[1]), "r"(a[2]), "r"(a[3]), "r"(b0), "r"(b1));
}
__device__ __forceinline__ void cp16(uint32_t dst, const void* src) {
    asm volatile("cp.async.cg.shared.global [%0], [%1], 16;" :: "r"(dst), "l"(src));
}
#define CP_COMMIT() asm volatile("cp.async.commit_group;" ::: "memory")
#define CP_WAIT0()  asm volatile("cp.async.wait_group 0;" ::: "memory")

__device__ __forceinline__ uint32_t pack_hl(float v) {
    __nv_bfloat16 h = __float2bfloat16(v);
    __nv_bfloat16 l = __float2bfloat16(v - __bfloat162float(h));
    return (uint32_t)__bfloat16_as_ushort(h) | ((uint32_t)__bfloat16_as_ushort(l) << 16);
}

// ---------------- scratch ----------------
__device__ uint32_t g_xP[BSZ * CCH * HWN];
__device__ uint32_t g_hP[BSZ * CCH * HWN];
__device__ float    g_mp[4 * MP_STRIDE];
__device__ float    g_op[4 * OP_STRIDE];
__device__ float    g_mod[BSZ * 36 * HWN];

// uniform parts: 38 parts x 18 chunks x 24 rows x 32
#define PART_ELEMS (18*24*32)       // 13824
#define W_TOTAL    (38*PART_ELEMS)  // 525312
__device__ __nv_bfloat16 g_wHi[W_TOTAL];
__device__ __nv_bfloat16 g_wLo[W_TOTAL];

// ---------------- transpose + bf16-split-pack ----------------
__global__ void transpose_kernel(const float* __restrict__ x, uint32_t* __restrict__ xP) {
    __shared__ float tile[32][33];
    int b  = blockIdx.z;
    int n0 = blockIdx.x * 32;
    int c0 = blockIdx.y * 32;
    int tx = threadIdx.x, ty = threadIdx.y;
    #pragma unroll
    for (int i = ty; i < 32; i += 8)
        tile[i][tx] = x[((size_t)b*HWN + n0 + i)*CCH + c0 + tx];
    __syncthreads();
    #pragma unroll
    for (int i = ty; i < 32; i += 8)
        xP[((size_t)b*CCH + c0 + i)*HWN + n0 + tx] = pack_hl(tile[tx][i]);
}

// ---------------- weight prepack (38 uniform parts, rowsPad=24) ----------------
struct PackPart { const float* w; int wCinG, nInW0, ciInW0, CoutValid; };
struct PackAll  { PackPart p[38]; };

__global__ void prepack_kernel(PackAll a) {
    long e = (long)blockIdx.x * 256 + threadIdx.x;
    int q = (int)(e / PART_ELEMS);
    if (q >= 38) return;
    int e2 = (int)(e - (long)q * PART_ELEMS);
    PackPart pp = a.p[q];
    int chunk = e2 / (24 * 32);
    int r     = e2 - chunk * (24 * 32);
    int row = r >> 5, j = r & 31;
    int cb = chunk / 9, tap = chunk - cb * 9;
    float v = 0.f;
    if (row < pp.CoutValid)
        v = pp.w[(((size_t)(pp.nInW0 + row)) * pp.wCinG + pp.ciInW0 + cb * 32 + j) * 9 + tap];
    __nv_bfloat16 h = __float2bfloat16(v);
    long dst = (long)q * PART_ELEMS + e2;
    g_wHi[dst] = h;
    g_wLo[dst] = __float2bfloat16(v - __bfloat162float(h));
}

// ---------------- implicit-GEMM conv via mma.sync (3-pass bf16 split) ----------------
// NFR=3 (24 couts). Per cin-chunk: stage A + ALL 9 taps' B, then 9 taps BARRIER-FREE.
struct ConvPart {
    const void* in;
    long inStride; int nPart;
    int inPacked, inAct;
    const __nv_bfloat16 *wHi, *wLo;    // pre-offset to part base
    const float* bias;                  // pre-offset to coutBase
    void* out;
    int cinTotal, ciBase, coutTotal, coutBase, CoutValid, nCb, act, outPacked, addBias;
};
struct ConvArgs { ConvPart p[24]; };

#define NFR   3
#define A_SZ  (4*66*80)            // 21120 per array (hi, lo)
#define SMB   (2*A_SZ)             // 42240
#define BCH   (NFR*8*80)           // 1920 per array per chunk
#define SMTOT (SMB + 9*2*BCH)      // 76800

// stage all 9 taps' B (hi+lo) for cin-block cb
__device__ __forceinline__ void stage_b_all(uint32_t sb,
        const __nv_bfloat16* wHi, const __nv_bfloat16* wLo, int cb, int tid) {
    const int NV = NFR * 32;                 // 96 uint4 per array per chunk
    const int TOTAL = 9 * 2 * NV;            // 1728
    const char* gH = (const char*)(wHi + (size_t)cb * 9 * (NFR*8*32));
    const char* gL = (const char*)(wLo + (size_t)cb * 9 * (NFR*8*32));
    #pragma unroll
    for (int r = 0; r < (TOTAL + 255)/256; r++) {
        int i = tid + r*256;
        if (i < TOTAL) {
            int c   = i / (2*NV);
            int rem = i - c*(2*NV);
            int arr = (rem >= NV);
            int ii  = rem - (arr ? NV : 0);
            uint32_t dst = sb + SMB + (uint32_t)(c*2 + arr)*BCH + (ii>>2)*80 + (ii&3)*16;
            const char* src = (arr ? gL : gH) + (size_t)c*(NFR*8*32*2) + ii*16;
            cp16(dst, src);
        }
    }
}

__global__ void __launch_bounds__(256, 3) conv_mma(ConvArgs args) {
    extern __shared__ char smem[];
    const ConvPart P = args.p[blockIdx.y];
    const int tid = threadIdx.x;
    const int wid = tid >> 5, lid = tid & 31;
    const int b  = blockIdx.x >> 5;
    const int r0 = (blockIdx.x & 31) << 1;      // 2 image rows -> 128 pixels
    uint32_t sb = smem_u32(smem);

    float acc[NFR][4];
    #pragma unroll
    for (int i = 0; i < NFR; i++) { acc[i][0]=acc[i][1]=acc[i][2]=acc[i][3]=0.f; }

    const int mPix = wid * 16 + (lid & 15);
    const int yloc = mPix >> 6, xpix = mPix & 63;
    const uint32_t aOfs = (uint32_t)(((yloc + 1) * 66 + (xpix + 1)) * 80) + ((lid >> 4) * 16);
    const int nloc4  = (lid & 7) + ((lid >> 4) << 3);
    const int khalfB = ((lid >> 3) & 1) * 16;

    // zero border cols px=0, px=65 (x=-1, x=64 always OOB)
    for (int i = tid; i < 4*64; i += 256) {
        int side = i & 1, rr = (i >> 1) & 3, j = (i >> 1) >> 2;
        uint32_t o = (uint32_t)(rr*66 + side*65) * 80 + j*2;
        *(uint16_t*)(smem + o)        = 0;
        *(uint16_t*)(smem + A_SZ + o) = 0;
    }
    __syncthreads();

    #pragma unroll 1
    for (int cb = 0; cb < P.nCb; cb++) {
        const size_t chBase = ((size_t)(b * P.cinTotal + P.ciBase + cb * 32)) * HWN;
        // ---- stage A patch ----
        if (P.inPacked) {
            const uint32_t* ip = (const uint32_t*)P.in + chBase;
            const int j = tid >> 3;
            const int lane8 = tid & 7;
            const uint32_t* cp = ip + (size_t)j * HWN;
            #pragma unroll
            for (int py = 0; py < 4; py++) {
                int y = r0 - 1 + py;
                bool vy = ((unsigned)y < HH);
                const uint32_t* rp = cp + y * WW;
                #pragma unroll
                for (int it = 0; it < 4; it++) {
                    int p = lane8 + it * 8;
                    uint2 v = make_uint2(0u, 0u);
                    if (vy) v = *(const uint2*)(rp + 2*p);
                    uint32_t o = (uint32_t)(py*66 + 1 + 2*p) * 80 + j*2;
                    *(uint16_t*)(smem + o)             = (uint16_t)v.x;
                    *(uint16_t*)(smem + A_SZ + o)      = (uint16_t)(v.x >> 16);
                    *(uint16_t*)(smem + o + 80)        = (uint16_t)v.y;
                    *(uint16_t*)(smem + A_SZ + o + 80) = (uint16_t)(v.y >> 16);
                }
            }
        } else {
            const float* ip = (const float*)P.in + chBase;
            for (int i = tid; i < 4 * 66 * 32; i += 256) {
                int j   = i / 264;
                int pix = i - j * 264;
                int py = pix / 66, px = pix - py * 66;
                int y = r0 - 1 + py, x = px - 1;
                float v = 0.f;
                if ((unsigned)y < HH && (unsigned)x < WW) {
                    size_t idx = (size_t)j * HWN + y * WW + x;
                    v = ip[idx];
                    for (int k = 1; k < P.nPart; k++) v += ip[idx + (size_t)k * P.inStride];
                    if (P.inAct) v = v * normcdff(v);
                }
                __nv_bfloat16 h = __float2bfloat16(v);
                __nv_bfloat16 l = __float2bfloat16(v - __bfloat162float(h));
                uint32_t o = (uint32_t)(py * 66 + px) * 80 + j * 2;
                *(__nv_bfloat16*)(smem + o)        = h;
                *(__nv_bfloat16*)(smem + A_SZ + o) = l;
            }
        }
        // ---- stage ALL 9 taps' B (async) ----
        stage_b_all(sb, P.wHi, P.wLo, cb, tid);
        CP_COMMIT();
        CP_WAIT0();
        __syncthreads();

        // ---- 9 taps, BARRIER-FREE (A and B read-only for this chunk) ----
        #pragma unroll
        for (int tap = 0; tap < 9; tap++) {
            const int dy = tap / 3 - 1, dx = tap % 3 - 1;
            const int dOfs = (dy * 66 + dx) * 80;
            const uint32_t bBase = sb + SMB + (uint32_t)(tap * 2) * BCH;
            #pragma unroll
            for (int k16 = 0; k16 < 2; k16++) {
                uint32_t ah[4], al[4];
                ldsm_x4(ah, sb + aOfs + dOfs + k16 * 32);
                ldsm_x4(al, sb + (uint32_t)A_SZ + aOfs + dOfs + k16 * 32);
                // nf 0,1 via x4
                {
                    uint32_t bAddr = bBase + (uint32_t)nloc4 * 80 + k16 * 32 + khalfB;
                    uint32_t bh[4], bl[4];
                    ldsm_x4(bh, bAddr);
                    ldsm_x4(bl, bAddr + BCH);
                    mma_bf16(acc[0], ah, bh[0], bh[1]);
                    mma_bf16(acc[1], ah, bh[2], bh[3]);
                    mma_bf16(acc[0], al, bh[0], bh[1]);
                    mma_bf16(acc[1], al, bh[2], bh[3]);
                    mma_bf16(acc[0], ah, bl[0], bl[1]);
                    mma_bf16(acc[1], ah, bl[2], bl[3]);
                }
                // nf 2 via x2
                {
                    uint32_t bAddr = bBase + (uint32_t)(16 + (lid & 7)) * 80 + k16 * 32 + khalfB;
                    uint32_t bh[2], bl[2];
                    ldsm_x2(bh, bAddr);
                    ldsm_x2(bl, bAddr + BCH);
                    mma_bf16(acc[2], ah, bh[0], bh[1]);
                    mma_bf16(acc[2], al, bh[0], bh[1]);
                    mma_bf16(acc[2], ah, bl[0], bl[1]);
                }
            }
        }
        __syncthreads();   // protect A/B before next chunk's staging (and epilogue overlay)
    }

    // epilogue via smem transpose
    float* sd = (float*)smem;
    {
        const int rr = lid >> 2, cc = (lid & 3) * 2;
        const int mB = wid * 16;
        #pragma unroll
        for (int nf = 0; nf < NFR; nf++) {
            int n = nf * 8 + cc;
            sd[(n    ) * 132 + mB + rr    ] = acc[nf][0];
            sd[(n + 1) * 132 + mB + rr    ] = acc[nf][1];
            sd[(n    ) * 132 + mB + rr + 8] = acc[nf][2];
            sd[(n + 1) * 132 + mB + rr + 8] = acc[nf][3];
        }
    }
    __syncthreads();
    const int pixBase = r0 * WW;
    for (int i = tid; i < P.CoutValid * 128; i += 256) {
        int n = i >> 7, mm = i & 127;
        float v = sd[n * 132 + mm] + (P.addBias ? P.bias[n] : 0.f);
        if (P.act == 1)      v = v * normcdff(v);
        else if (P.act == 2) v = 1.f / (1.f + expf(-v));
        size_t oidx = ((size_t)(b * P.coutTotal + P.coutBase + n)) * HWN + pixBase + mm;
        if (P.outPacked) ((uint32_t*)P.out)[oidx] = pack_hl(v);
        else             ((float*)P.out)[oidx] = v;
    }
}

// ---------------- deformable sampling ----------------
__global__ void __launch_bounds__(256) sample_kernel(
    const float* __restrict__ x,
    const float* __restrict__ op,
    const float* __restrict__ mod,
    float* __restrict__ out)
{
    __shared__ float4 sw[36];
    __shared__ int4   so[36];

    const int t    = threadIdx.x;
    const int c    = t & 63;
    const int pl   = t >> 6;
    const int pix0 = blockIdx.x * 4;
    const int g    = blockIdx.y;
    const int b    = blockIdx.z;

    if (t < 36) {
        const int pli = t / 9;
        const int p   = t - pli * 9;
        const int pix = pix0 + pli;
        const int yq  = pix >> 6;
        const int xq  = pix & 63;

        const float* offp = op  + ((size_t)b*72 + g*18)*HWN + pix;
        const float* modp = mod + ((size_t)b*36 + g*9 )*HWN + pix;

        float ox = 0.f, oy = 0.f;
        #pragma unroll
        for (int k = 0; k < 4; k++) {
            ox += offp[(size_t)k*OP_STRIDE + (size_t)p*HWN];
            oy += offp[(size_t)k*OP_STRIDE + (size_t)(9+p)*HWN];
        }
        float mv = modp[(size_t)p*HWN] * (1.f/9.f);

        float px = fminf(fmaxf((float)(xq + (p%3) - 1) + ox, 0.f), (float)(WW-1));
        float py = fminf(fmaxf((float)(yq + (p/3) - 1) + oy, 0.f), (float)(HH-1));

        float x0f = floorf(px), y0f = floorf(py);
        float wx = px - x0f, wy = py - y0f;
        int x0 = (int)x0f, y0 = (int)y0f;
        int x1 = min(x0 + 1, WW-1);
        int y1 = min(y0 + 1, HH-1);

        sw[t] = make_float4((1.f-wx)*(1.f-wy)*mv, wx*(1.f-wy)*mv,
                            (1.f-wx)*wy*mv,       wx*wy*mv);
        so[t] = make_int4((y0*WW + x0)*CCH, (y0*WW + x1)*CCH,
                          (y1*WW + x0)*CCH, (y1*WW + x1)*CCH);
    }
    __syncthreads();

    const float* xb = x + (size_t)b*HWN*CCH + g*CG + c;
    float acc = 0.f;
    #pragma unroll
    for (int p = 0; p < 9; p++) {
        float4 w = sw[pl*9 + p];
        int4   o = so[pl*9 + p];
        float v00 = __ldg(xb + o.x);
        float v01 = __ldg(xb + o.y);
        float v10 = __ldg(xb + o.z);
        float v11 = __ldg(xb + o.w);
        acc += v00*w.x + v01*w.y + v10*w.z + v11*w.w;
    }
    out[((size_t)b*HWN + pix0 + pl)*CCH + g*CG + c] = acc;
}

// ---------------- launch ----------------
extern "C" void kernel_launch(void* const* d_in, const int* in_sizes, int n_in,
                              void* d_out, int out_size)
{
    const float* x      = (const float*)d_in[0];
    const float* off_w1 = (const float*)d_in[1];
    const float* off_b1 = (const float*)d_in[2];
    const float* off_w2 = (const float*)d_in[3];
    const float* off_b2 = (const float*)d_in[4];
    const float* mod_w1 = (const float*)d_in[5];
    const float* mod_b1 = (const float*)d_in[6];
    const float* mod_w2 = (const float*)d_in[7];
    const float* mod_b2 = (const float*)d_in[8];
    float* out = (float*)d_out;

    uint32_t *xP, *hP;
    float *mp, *op, *md;
    cudaGetSymbolAddress((void**)&xP, g_xP);
    cudaGetSymbolAddress((void**)&hP, g_hP);
    cudaGetSymbolAddress((void**)&mp, g_mp);
    cudaGetSymbolAddress((void**)&op, g_op);
    cudaGetSymbolAddress((void**)&md, g_mod);

    __nv_bfloat16 *wHi, *wLo;
    cudaGetSymbolAddress((void**)&wHi, g_wHi);
    cudaGetSymbolAddress((void**)&wLo, g_wLo);

    cudaFuncSetAttribute((const void*)conv_mma, cudaFuncAttributeMaxDynamicSharedMemorySize, SMTOT);

    // 1) transpose + pack
    {
        dim3 grid(HWN/32, CCH/32, BSZ), blk(32, 8);
        transpose_kernel<<<grid, blk>>>(x, xP);
    }
    // 2) weight prepack: 38 uniform parts (rowsPad 24)
    // order: [0..11]  mod1 (k=0..3) x (ns=0..2)
    //        [12..23] off1 (g=0..3) x (ns=0..2)
    //        [24..35] off2 (k=0..3) x (ns=0..2)
    //        [36..37] mod2 (ns=0..1)
    {
        PackAll pa;
        int idx = 0;
        for (int k = 0; k < 4; k++)
            for (int ns = 0; ns < 3; ns++)
                pa.p[idx++] = { mod_w1, 256, ns*24, k*64, ns == 2 ? 16 : 24 };
        for (int g = 0; g < 4; g++)
            for (int ns = 0; ns < 3; ns++)
                pa.p[idx++] = { off_w1, 64, g*64 + ns*24, 0, ns == 2 ? 16 : 24 };
        for (int k = 0; k < 4; k++)
            for (int ns = 0; ns < 3; ns++)
                pa.p[idx++] = { off_w2, 256, ns*24, k*64, 24 };
        for (int ns = 0; ns < 2; ns++)
            pa.p[idx++] = { mod_w2, 64, ns*24, 0, ns ? 12 : 24 };
        long total = 38L * PART_ELEMS;
        prepack_kernel<<<(int)((total + 255)/256), 256>>>(pa);
    }
    // 3) stage 1: 24 parts (mod1 12 + off1 12), grid 128x24
    {
        ConvArgs a;
        int idx = 0;
        for (int k = 0; k < 4; k++)
            for (int ns = 0; ns < 3; ns++) {
                ConvPart& P = a.p[idx];
                P.in = xP; P.inStride = 0; P.nPart = 1; P.inPacked = 1; P.inAct = 0;
                P.wHi = wHi + (size_t)idx*PART_ELEMS; P.wLo = wLo + (size_t)idx*PART_ELEMS;
                P.bias = mod_b1 + ns*24; P.out = mp + (size_t)k*MP_STRIDE;
                P.cinTotal = 256; P.ciBase = k*64; P.coutTotal = 64; P.coutBase = ns*24;
                P.CoutValid = ns == 2 ? 16 : 24; P.nCb = 2; P.act = 0; P.outPacked = 0; P.addBias = (k == 0);
                idx++;
            }
        for (int g = 0; g < 4; g++)
            for (int ns = 0; ns < 3; ns++) {
                ConvPart& P = a.p[idx];
                P.in = xP; P.inStride = 0; P.nPart = 1; P.inPacked = 1; P.inAct = 0;
                P.wHi = wHi + (size_t)idx*PART_ELEMS; P.wLo = wLo + (size_t)idx*PART_ELEMS;
                P.bias = off_b1 + g*64 + ns*24; P.out = hP;
                P.cinTotal = 256; P.ciBase = g*64; P.coutTotal = 256; P.coutBase = g*64 + ns*24;
                P.CoutValid = ns == 2 ? 16 : 24; P.nCb = 2; P.act = 1; P.outPacked = 1; P.addBias = 1;
                idx++;
            }
        conv_mma<<<dim3(128, 24), 256, SMTOT>>>(a);
    }
    // 4) stage 2: 14 parts (off2 12 + mod2 2), grid 128x14
    {
        ConvArgs a;
        int idx = 0;
        for (int k = 0; k < 4; k++)
            for (int ns = 0; ns < 3; ns++) {
                ConvPart& P = a.p[idx];
                int wpart = 24 + idx;
                P.in = hP; P.inStride = 0; P.nPart = 1; P.inPacked = 1; P.inAct = 0;
                P.wHi = wHi + (size_t)wpart*PART_ELEMS; P.wLo = wLo + (size_t)wpart*PART_ELEMS;
                P.bias = off_b2 + ns*24; P.out = op + (size_t)k*OP_STRIDE;
                P.cinTotal = 256; P.ciBase = k*64; P.coutTotal = 72; P.coutBase = ns*24;
                P.CoutValid = 24; P.nCb = 2; P.act = 0; P.outPacked = 0; P.addBias = (k == 0);
                idx++;
            }
        for (int ns = 0; ns < 2; ns++) {
            ConvPart& Q = a.p[idx];
            int wpart = 36 + ns;
            Q.in = mp; Q.inStride = MP_STRIDE; Q.nPart = 4; Q.inPacked = 0; Q.inAct = 1;
            Q.wHi = wHi + (size_t)wpart*PART_ELEMS; Q.wLo = wLo + (size_t)wpart*PART_ELEMS;
            Q.bias = mod_b2 + ns*24; Q.out = md;
            Q.cinTotal = 64; Q.ciBase = 0; Q.coutTotal = 36; Q.coutBase = ns*24;
            Q.CoutValid = ns ? 12 : 24; Q.nCb = 2; Q.act = 2; Q.outPacked = 0; Q.addBias = 1;
            idx++;
        }
        conv_mma<<<dim3(128, 14), 256, SMTOT>>>(a);
    }
    // 5) sampling
    {
        dim3 grid(HWN/4, GG, BSZ);
        sample_kernel<<<grid, 256>>>(x, op, md, out);
    }
}